// round 15
// baseline (speedup 1.0000x reference)
#include <cuda_runtime.h>
#include <cuda_bf16.h>

// dLDS_continuous: out[b] = expm(sum_m c[b,m] * G[m]) @ x[b]
// B = 2097152, N = 3, M = 6.
//
// Cayley-Hamilton coefficient-space expm, packed f32x2, 2 batches/thread,
// s=2 + deg-12 folded-constant Horner Taylor, __constant__ packed constants
// (R13 algorithm, unchanged).
// R14: block size 256 -> 160. At 44 regs/thread the register file packs
// 9 blocks x 160 = 45 warps/SM (70.3% theoretical) vs 5 x 256 = 40 warps
// (62.5%). Same regs, no spill risk — pure warp-supply experiment.

static constexpr int B_TOTAL = 2097152;
static constexpr int THREADS = 160;
static constexpr unsigned PAIRS = B_TOTAL / 2;   // 1048576

typedef unsigned long long u64;

// packed constants, both lanes equal; indexed as u64
// 0:SC1(1/4)  1:SC2N(-1/16)  2:SC3(1/64)  3:FOLD2(1/16)  4:NRM(1/12!)
// 5:W0(132)   6:W1(12)       7:ONE(1)     8..17: MJ = 12!/j!, j=9..0
__constant__ float2 KC[18] = {
    {0.25f, 0.25f},
    {-0.0625f, -0.0625f},
    {0.015625f, 0.015625f},
    {0.0625f, 0.0625f},
    {1.f / 479001600.f, 1.f / 479001600.f},
    {132.f, 132.f},
    {12.f, 12.f},
    {1.f, 1.f},
    {1320.f, 1320.f},
    {11880.f, 11880.f},
    {95040.f, 95040.f},
    {665280.f, 665280.f},
    {3991680.f, 3991680.f},
    {19958400.f, 19958400.f},
    {79833600.f, 79833600.f},
    {239500800.f, 239500800.f},
    {479001600.f, 479001600.f},
    {479001600.f, 479001600.f},
};

__device__ __forceinline__ u64 pk(float a, float b) {
    u64 r; asm("mov.b64 %0, {%1,%2};" : "=l"(r) : "f"(a), "f"(b)); return r;
}
__device__ __forceinline__ void upk(u64 v, float& a, float& b) {
    asm("mov.b64 {%0,%1}, %2;" : "=f"(a), "=f"(b) : "l"(v));
}
__device__ __forceinline__ u64 f2fma(u64 a, u64 b, u64 c) {
    u64 r; asm("fma.rn.f32x2 %0, %1, %2, %3;" : "=l"(r) : "l"(a), "l"(b), "l"(c)); return r;
}
__device__ __forceinline__ u64 f2mul(u64 a, u64 b) {
    u64 r; asm("mul.rn.f32x2 %0, %1, %2;" : "=l"(r) : "l"(a), "l"(b)); return r;
}
__device__ __forceinline__ u64 f2add(u64 a, u64 b) {
    u64 r; asm("add.rn.f32x2 %0, %1, %2;" : "=l"(r) : "l"(a), "l"(b)); return r;
}
__device__ __forceinline__ u64 f2sub(u64 a, u64 b) {
    u64 r; asm("sub.rn.f32x2 %0, %1, %2;" : "=l"(r) : "l"(a), "l"(b)); return r;
}

__global__ void __launch_bounds__(THREADS)
expm_apply_kernel(const float* __restrict__ x,
                  const float* __restrict__ c,
                  const float* __restrict__ G,
                  float* __restrict__ out)
{
    const u64* kc = reinterpret_cast<const u64*>(KC);

    // rows padded to 10 u64: 16B-aligned pairs -> ld.shared.v2.u64
    __shared__ alignas(16) u64 sG[60];
    int tid = threadIdx.x;
    unsigned t = blockIdx.x * THREADS + tid;   // pair index: batches 2t, 2t+1
    bool live = (t < PAIRS);
    unsigned ts = live ? t : 0;                // safe index for loads

    // ---- per-thread global loads hoisted above barrier (overlap latency) ----
    const float4* c4 = reinterpret_cast<const float4*>(c) + ts * 3u;
    float4 q0 = c4[0];
    float4 q1 = c4[1];
    float4 q2 = c4[2];
    const float2* x2 = reinterpret_cast<const float2*>(x) + ts * 3u;
    float2 xa = x2[0];
    float2 xb = x2[1];
    float2 xc = x2[2];

    if (tid < 54) {
        int m = tid / 9, k = tid % 9;
        float g = G[tid];
        sG[m * 10 + k] = pk(g, g);
    }
    __syncthreads();

    u64 X0, X1, X2, Y0, Y1, Y2, Z0, Z1, Z2;
    u64 c0i, c1i, c2i;
    {
        u64 cc[6] = { pk(q0.x, q1.z), pk(q0.y, q1.w), pk(q0.z, q2.x),
                      pk(q0.w, q2.y), pk(q1.x, q2.z), pk(q1.y, q2.w) };

        // ---- T = sum_m c[m]*G[m]; G rows via 4x LDS.128 + 1x LDS.64 ----
        u64 A[9];
#pragma unroll
        for (int m = 0; m < 6; ++m) {
            const u64* row = &sG[m * 10];
            u64 cm = cc[m];
#pragma unroll
            for (int kp = 0; kp < 4; ++kp) {
                ulonglong2 g2 = *reinterpret_cast<const ulonglong2*>(row + 2 * kp);
                if (m == 0) {
                    A[2 * kp]     = f2mul(cm, g2.x);
                    A[2 * kp + 1] = f2mul(cm, g2.y);
                } else {
                    A[2 * kp]     = f2fma(cm, g2.x, A[2 * kp]);
                    A[2 * kp + 1] = f2fma(cm, g2.y, A[2 * kp + 1]);
                }
            }
            u64 g8 = row[8];
            if (m == 0) A[8] = f2mul(cm, g8);
            else        A[8] = f2fma(cm, g8, A[8]);
        }

        // ---- invariants of T ----
        u64 I1 = f2add(f2add(A[0], A[4]), A[8]);
        u64 m0 = f2sub(f2mul(A[4], A[8]), f2mul(A[5], A[7]));
        u64 m1 = f2sub(f2mul(A[0], A[8]), f2mul(A[2], A[6]));
        u64 m2 = f2sub(f2mul(A[0], A[4]), f2mul(A[1], A[3]));
        u64 I2 = f2add(f2add(m0, m1), m2);
        u64 u1 = f2sub(f2mul(A[3], A[8]), f2mul(A[5], A[6]));
        u64 u2 = f2sub(f2mul(A[3], A[7]), f2mul(A[4], A[6]));
        u64 I3 = f2fma(A[0], m0, f2sub(f2mul(A[2], u2), f2mul(A[1], u1)));

        // char poly of As = T/4:  As^3 = c0 I + c1 As + c2 As^2  (s = 2)
        c2i = f2mul(I1, kc[0]);    // * 1/4
        c1i = f2mul(I2, kc[1]);    // * -1/16
        c0i = f2mul(I3, kc[2]);    // * 1/64

        // ---- early matvecs: y = T x, z = T y (A dies here) ----
        X0 = pk(xa.x, xb.y);
        X1 = pk(xa.y, xc.x);
        X2 = pk(xb.x, xc.y);
        Y0 = f2fma(A[0], X0, f2fma(A[1], X1, f2mul(A[2], X2)));
        Y1 = f2fma(A[3], X0, f2fma(A[4], X1, f2mul(A[5], X2)));
        Y2 = f2fma(A[6], X0, f2fma(A[7], X1, f2mul(A[8], X2)));
        Z0 = f2fma(A[0], Y0, f2fma(A[1], Y1, f2mul(A[2], Y2)));
        Z1 = f2fma(A[3], Y0, f2fma(A[4], Y1, f2mul(A[5], Y2)));
        Z2 = f2fma(A[6], Y0, f2fma(A[7], Y1, f2mul(A[8], Y2)));
    }

    // ---- Taylor deg 12, folded-constant Horner in triple space ----
    // W_j = As*W_{j+1} + (12!/j!) I ; after two trivial iters W = (132, 12, 1).
    u64 w0 = kc[5];
    u64 w1 = kc[6];
    u64 w2 = kc[7];
#pragma unroll
    for (int k = 0; k < 10; ++k) {
        u64 Mj = kc[8 + k];
        u64 nw0 = f2fma(w2, c0i, Mj);
        u64 nw1 = f2fma(w2, c1i, w0);
        u64 nw2 = f2fma(w2, c2i, w1);
        w0 = nw0; w1 = nw1; w2 = nw2;
    }
    // normalize: E = W / 12!
    u64 a0 = f2mul(w0, kc[4]);
    u64 a1 = f2mul(w1, kc[4]);
    u64 a2 = f2mul(w2, kc[4]);

    // ---- As^4 reduction triple ----
    u64 d0 = f2mul(c2i, c0i);
    u64 d1 = f2fma(c2i, c1i, c0i);
    u64 d2 = f2fma(c2i, c2i, c1i);

    // ---- 2 squarings in coefficient space (s = 2) ----
#pragma unroll
    for (int it = 0; it < 2; ++it) {
        u64 q01 = f2mul(a0, a1);
        u64 q02 = f2mul(a0, a2);
        u64 q12 = f2mul(a1, a2);
        u64 q22 = f2mul(a2, a2);
        u64 t12 = f2add(q12, q12);
        u64 b0 = f2fma(q22, d0, f2fma(t12, c0i, f2mul(a0, a0)));
        u64 b1 = f2fma(q22, d1, f2fma(t12, c1i, f2add(q01, q01)));
        u64 b2 = f2fma(q22, d2, f2fma(t12, c2i, f2fma(a1, a1, f2add(q02, q02))));
        a0 = b0; a1 = b1; a2 = b2;
    }
    // fold 2^-2 / 2^-4 (y, z were computed with raw T)
    a1 = f2mul(a1, kc[0]);   // * 1/4
    a2 = f2mul(a2, kc[3]);   // * 1/16

    // ---- out = a0*x + a1*y + a2*z ----
    u64 O0 = f2fma(a0, X0, f2fma(a1, Y0, f2mul(a2, Z0)));
    u64 O1 = f2fma(a0, X1, f2fma(a1, Y1, f2mul(a2, Z1)));
    u64 O2 = f2fma(a0, X2, f2fma(a1, Y2, f2mul(a2, Z2)));

    float o0l, o0h, o1l, o1h, o2l, o2h;
    upk(O0, o0l, o0h);
    upk(O1, o1l, o1h);
    upk(O2, o2l, o2h);

    if (live) {
        float2* ob = reinterpret_cast<float2*>(out) + t * 3u;
        ob[0] = make_float2(o0l, o1l);
        ob[1] = make_float2(o2l, o0h);
        ob[2] = make_float2(o1h, o2h);
    }
}

extern "C" void kernel_launch(void* const* d_in, const int* in_sizes, int n_in,
                              void* d_out, int out_size)
{
    const float* x = (const float*)d_in[0];   // (B, 3, 1)
    const float* c = (const float*)d_in[1];   // (B, 6)
    const float* G = (const float*)d_in[2];   // (6, 3, 3)
    float* out = (float*)d_out;               // (B, 3, 1)

    unsigned grid = (PAIRS + THREADS - 1) / THREADS;   // 6554 blocks
    expm_apply_kernel<<<grid, THREADS>>>(x, c, G, out);
}